// round 16
// baseline (speedup 1.0000x reference)
#include <cuda_runtime.h>
#include <cuda_bf16.h>
#include <cuda_fp16.h>
#include <math.h>
#include <stdint.h>

// Problem dims (fixed): x[8,1024,1024], w1[4096,1024], w2[1024,4096]
#define DIM 1024
#define HID 4096
#define TOK 8192   // B*S

// tcgen05 is arch-SPECIFIC: only emit in sm_103a/sm_100a-family passes.
#if defined(__CUDA_ARCH_FEAT_SM103_ALL) || defined(__CUDA_ARCH_FEAT_SM100_ALL) || \
    defined(__CUDA_ARCH_FEAT_SM101_ALL) || defined(__CUDA_ARCH_FEAT_SM110_ALL)
#define TC_OK 1
#else
#define TC_OK 0
#endif

// ---------------- scratch (device globals; no allocations allowed) ----------------
__device__ __half g_xq[(size_t)TOK * DIM];   // LN1 out (fp16)      16MB
__device__ __half g_h [(size_t)TOK * HID];   // GEMM1+GELU out      64MB
__device__ __half g_hq[(size_t)TOK * HID];   // LN2 out (fp16)      64MB
__device__ __half g_t1[(size_t)HID * DIM];   // ternary w1 (fp16)    8MB
__device__ __half g_t2[(size_t)DIM * HID];   // ternary w2 (fp16)    8MB
__device__ float g_partial[2][256];
__device__ float g_scale[2];     // 1/mean|w|
__device__ float g_mul[2];       // mean|w|

// ---------------- small helpers ----------------
__device__ __forceinline__ float warp_sum(float v) {
#pragma unroll
    for (int o = 16; o > 0; o >>= 1) v += __shfl_xor_sync(0xffffffffu, v, o);
    return v;
}
__device__ __forceinline__ float block_sum_256(float v) {
    __shared__ float sh[8];
    v = warp_sum(v);
    if ((threadIdx.x & 31) == 0) sh[threadIdx.x >> 5] = v;
    __syncthreads();
    float tot = 0.f;
    if (threadIdx.x == 0) {
#pragma unroll
        for (int i = 0; i < 8; i++) tot += sh[i];
        sh[0] = tot;
    }
    __syncthreads();
    tot = sh[0];
    __syncthreads();
    return tot;
}
__device__ __forceinline__ uint32_t smem_u32(const void* p) {
    uint32_t a;
    asm("{ .reg .u64 t; cvta.to.shared.u64 t, %1; cvt.u32.u64 %0, t; }" : "=r"(a) : "l"(p));
    return a;
}
#define SW128(o) ((o) ^ (((o) >> 3) & 0x70))

static constexpr uint64_t SMEM_DESC_BASE =
    (uint64_t(2) << 61) | (uint64_t(1) << 46) | (uint64_t(64) << 32) | (uint64_t(1) << 16);
__device__ __forceinline__ uint64_t make_desc(uint32_t addr) {
    return SMEM_DESC_BASE | ((uint64_t)(addr >> 4) & 0x3FFF);
}

// ---------------- PTX wrappers ----------------
__device__ __forceinline__ void cp16(uint32_t dst, const void* src) {
    asm volatile("cp.async.cg.shared.global [%0], [%1], 16;" :: "r"(dst), "l"(src));
}
__device__ __forceinline__ void cp_commit() {
    asm volatile("cp.async.commit_group;" ::: "memory");
}
template <int N>
__device__ __forceinline__ void cp_wait() {
    asm volatile("cp.async.wait_group %0;" :: "n"(N) : "memory");
}
__device__ __forceinline__ void mbar_init(uint32_t a, uint32_t cnt) {
    asm volatile("mbarrier.init.shared.b64 [%0], %1;" :: "r"(a), "r"(cnt) : "memory");
}
__device__ __forceinline__ void mbar_wait(uint32_t a, uint32_t parity) {
    asm volatile(
        "{\n\t.reg .pred P;\n\t"
        "MW_%=:\n\t"
        "mbarrier.try_wait.parity.acquire.cta.shared::cta.b64 P, [%0], %1;\n\t"
        "@!P bra MW_%=;\n\t}"
        :: "r"(a), "r"(parity) : "memory");
}
#define FENCE_ASYNC() asm volatile("fence.proxy.async.shared::cta;" ::: "memory")

#if TC_OK
__device__ __forceinline__ void tc_commit(uint32_t mbar) {
    asm volatile(
        "tcgen05.commit.cta_group::1.mbarrier::arrive::one.shared::cluster.b64 [%0];"
        :: "r"(mbar) : "memory");
}
__device__ __forceinline__ void mma_f16_ss(uint32_t d, uint64_t a_desc, uint64_t b_desc,
                                           uint32_t idesc, uint32_t accum) {
    asm volatile(
        "{\n\t.reg .pred p;\n\t"
        "setp.ne.u32 p, %4, 0;\n\t"
        "tcgen05.mma.cta_group::1.kind::f16 [%0], %1, %2, %3, {%5, %5, %5, %5}, p;\n\t}"
        :: "r"(d), "l"(a_desc), "l"(b_desc), "r"(idesc), "r"(accum), "r"(0u)
        : "memory");
}
#define TC_ALLOC(saddr, n) \
    asm volatile("tcgen05.alloc.cta_group::1.sync.aligned.shared::cta.b32 [%0], %1;" \
                 :: "r"(saddr), "r"((uint32_t)(n)) : "memory")
#define TC_RELINQ() \
    asm volatile("tcgen05.relinquish_alloc_permit.cta_group::1.sync.aligned;")
#define TC_DEALLOC(t, n) \
    asm volatile("tcgen05.dealloc.cta_group::1.sync.aligned.b32 %0, %1;" :: "r"(t), "r"((uint32_t)(n)))
#define TC_FENCE_AFTER()  asm volatile("tcgen05.fence::after_thread_sync;" ::: "memory")
#define TC_WAIT_LD()      asm volatile("tcgen05.wait::ld.sync.aligned;" ::: "memory")

#define LDTM_X32(r, addr) \
    asm volatile( \
        "tcgen05.ld.sync.aligned.32x32b.x32.b32 " \
        "{%0, %1, %2, %3, %4, %5, %6, %7, " \
        " %8, %9, %10, %11, %12, %13, %14, %15, " \
        " %16, %17, %18, %19, %20, %21, %22, %23, " \
        " %24, %25, %26, %27, %28, %29, %30, %31}, [%32];" \
        : "=r"((r)[0]),  "=r"((r)[1]),  "=r"((r)[2]),  "=r"((r)[3]), \
          "=r"((r)[4]),  "=r"((r)[5]),  "=r"((r)[6]),  "=r"((r)[7]), \
          "=r"((r)[8]),  "=r"((r)[9]),  "=r"((r)[10]), "=r"((r)[11]), \
          "=r"((r)[12]), "=r"((r)[13]), "=r"((r)[14]), "=r"((r)[15]), \
          "=r"((r)[16]), "=r"((r)[17]), "=r"((r)[18]), "=r"((r)[19]), \
          "=r"((r)[20]), "=r"((r)[21]), "=r"((r)[22]), "=r"((r)[23]), \
          "=r"((r)[24]), "=r"((r)[25]), "=r"((r)[26]), "=r"((r)[27]), \
          "=r"((r)[28]), "=r"((r)[29]), "=r"((r)[30]), "=r"((r)[31]) \
        : "r"(addr))
#endif  // TC_OK

// ---------------- stage 0: abs-mean of weights (float4) ----------------
__global__ void absmean_partial_kernel(const float* __restrict__ w, int n, int slot) {
    float s = 0.f;
    const float4* w4 = reinterpret_cast<const float4*>(w);
    int n4 = n >> 2;
    int stride = gridDim.x * blockDim.x;
    for (int i = blockIdx.x * blockDim.x + threadIdx.x; i < n4; i += stride) {
        float4 v = w4[i];
        s += fabsf(v.x) + fabsf(v.y) + fabsf(v.z) + fabsf(v.w);
    }
    s = block_sum_256(s);
    if (threadIdx.x == 0) g_partial[slot][blockIdx.x] = s;
}
__global__ void finalize_scales_kernel(int n1, int n2) {
    for (int slot = 0; slot < 2; slot++) {
        float v = g_partial[slot][threadIdx.x];
        float tot = block_sum_256(v);
        if (threadIdx.x == 0) {
            float mean = tot / (float)(slot == 0 ? n1 : n2);
            mean = fmaxf(mean, 1e-5f);
            g_mul[slot]   = mean;
            g_scale[slot] = 1.0f / mean;
        }
        __syncthreads();
    }
}

// ---------------- stage 1: ternary quantization -> fp16 (exact for {-1,0,1}) ------
__global__ void quant_kernel(const float* __restrict__ w, __half* __restrict__ t,
                             const float* __restrict__ scalep, int n) {
    float s = *scalep;
    const float4* w4 = reinterpret_cast<const float4*>(w);
    __half2* t2 = reinterpret_cast<__half2*>(t);
    int n4 = n >> 2;
    int stride = gridDim.x * blockDim.x;
    for (int i = blockIdx.x * blockDim.x + threadIdx.x; i < n4; i += stride) {
        float4 v = w4[i];
        float q0 = fmaxf(-1.f, fminf(1.f, rintf(v.x * s)));
        float q1 = fmaxf(-1.f, fminf(1.f, rintf(v.y * s)));
        float q2 = fmaxf(-1.f, fminf(1.f, rintf(v.z * s)));
        float q3 = fmaxf(-1.f, fminf(1.f, rintf(v.w * s)));
        t2[i * 2 + 0] = __floats2half2_rn(q0, q1);
        t2[i * 2 + 1] = __floats2half2_rn(q2, q3);
    }
}

// ---------------- LN1 (fp32 in, D=1024) -> fp16 ----------------
__global__ __launch_bounds__(256) void ln1_kernel(
    const float* __restrict__ x, __half* __restrict__ o,
    const float* __restrict__ gamma, const float* __restrict__ beta)
{
    constexpr int D = DIM;
    const int row = blockIdx.x;
    const float4* xr = reinterpret_cast<const float4*>(x + (size_t)row * D);
    float4 v = xr[threadIdx.x];
    float s = v.x + v.y + v.z + v.w;
    float sq = v.x * v.x + v.y * v.y + v.z * v.z + v.w * v.w;
    __shared__ float sh[16];
    float ws = warp_sum(s), wq = warp_sum(sq);
    if ((threadIdx.x & 31) == 0) { sh[threadIdx.x >> 5] = ws; sh[8 + (threadIdx.x >> 5)] = wq; }
    __syncthreads();
    __shared__ float s_mu, s_rstd;
    if (threadIdx.x == 0) {
        float ts = 0.f, tq = 0.f;
#pragma unroll
        for (int i = 0; i < 8; i++) { ts += sh[i]; tq += sh[8 + i]; }
        float mu = ts / (float)D;
        float var = tq / (float)D - mu * mu;
        s_mu = mu;
        s_rstd = rsqrtf(var + 1e-5f);
    }
    __syncthreads();
    const float mu = s_mu, rstd = s_rstd;
    const float4 g = reinterpret_cast<const float4*>(gamma)[threadIdx.x];
    const float4 b = reinterpret_cast<const float4*>(beta)[threadIdx.x];
    __half2* o2 = reinterpret_cast<__half2*>(o + (size_t)row * D);
    float o0 = (v.x - mu) * rstd * g.x + b.x;
    float o1 = (v.y - mu) * rstd * g.y + b.y;
    float o2v = (v.z - mu) * rstd * g.z + b.z;
    float o3 = (v.w - mu) * rstd * g.w + b.w;
    o2[threadIdx.x * 2 + 0] = __floats2half2_rn(o0, o1);
    o2[threadIdx.x * 2 + 1] = __floats2half2_rn(o2v, o3);
}

// ---------------- LN2 (fp16 in, D=4096) -> fp16 ----------------
__global__ __launch_bounds__(256) void ln2_kernel(
    const __half* __restrict__ x, __half* __restrict__ o,
    const float* __restrict__ gamma, const float* __restrict__ beta)
{
    constexpr int D = HID;
    const int row = blockIdx.x;
    const __half2* xr = reinterpret_cast<const __half2*>(x + (size_t)row * D);
    float2 f[8];
    float s = 0.f, sq = 0.f;
#pragma unroll
    for (int i = 0; i < 8; i++) {
        __half2 v = xr[threadIdx.x + i * 256];
        f[i] = __half22float2(v);
        s  += f[i].x + f[i].y;
        sq += f[i].x * f[i].x + f[i].y * f[i].y;
    }
    __shared__ float sh[16];
    float ws = warp_sum(s), wq = warp_sum(sq);
    if ((threadIdx.x & 31) == 0) { sh[threadIdx.x >> 5] = ws; sh[8 + (threadIdx.x >> 5)] = wq; }
    __syncthreads();
    __shared__ float s_mu, s_rstd;
    if (threadIdx.x == 0) {
        float ts = 0.f, tq = 0.f;
#pragma unroll
        for (int i = 0; i < 8; i++) { ts += sh[i]; tq += sh[8 + i]; }
        float mu = ts / (float)D;
        float var = tq / (float)D - mu * mu;
        s_mu = mu;
        s_rstd = rsqrtf(var + 1e-5f);
    }
    __syncthreads();
    const float mu = s_mu, rstd = s_rstd;
    const float2* g2p = reinterpret_cast<const float2*>(gamma);
    const float2* b2p = reinterpret_cast<const float2*>(beta);
    __half2* o2 = reinterpret_cast<__half2*>(o + (size_t)row * D);
#pragma unroll
    for (int i = 0; i < 8; i++) {
        int idx = threadIdx.x + i * 256;
        float2 g = g2p[idx], b = b2p[idx];
        float v0 = (f[i].x - mu) * rstd * g.x + b.x;
        float v1 = (f[i].y - mu) * rstd * g.y + b.y;
        o2[idx] = __floats2half2_rn(v0, v1);
    }
}

// ---------------- tcgen05 GEMM: 128x256 tiles, fp16, 2-stage, OCCUPANCY 2 --------
// C[M,N] = (A[M,K] . B[N,K]^T)*mul + bias; do_gelu -> exact GELU + fp16 out, else fp32 out
// 2 CTAs/SM (96KB smem + 256 TMEM cols each). Epilogue/drain of one CTA overlaps the
// other CTA's mainloop.
#define BM 128
#define BN 256
#define BK 64
#define TILE_A       16384                   // 128 rows x 128B (fp16 A)
#define TILE_B       32768                   // 256 rows x 128B
#define STAGE_BYTES  (TILE_A + TILE_B)       // 48KB
#define NSTAGE 2
#define SM_TMEMPTR   (NSTAGE * STAGE_BYTES)  // 98304
#define SM_MBAR      (SM_TMEMPTR + 8)        // 2 mbars
#define SMEM_TOTAL   (SM_TMEMPTR + 64)       // 98368 -> 2 CTAs/SM
// idesc: f32 accum (dtype=1), fp16 A/B (atype=btype=0), N=128, M=128
#define MMA_IDESC 0x8200010u

__device__ __forceinline__ void load_chunk(
    const __half* __restrict__ A, const __half* __restrict__ Bt,
    int K, int bm, int bn, int k0, uint32_t sbase)
{
    const int t = threadIdx.x;
#pragma unroll
    for (int i = 0; i < 4; i++) {
        int idx = t + (i << 8);   // A rows 0..127, 8x16B chunks each
        int row = idx >> 3;
        int c   = idx & 7;
        uint32_t sw = SW128(row * 128 + c * 16);
        cp16(sbase + sw, A + (size_t)(bm + row) * K + k0 + c * 8);
    }
#pragma unroll
    for (int i = 0; i < 8; i++) {
        int idx = t + (i << 8);   // B rows 0..255
        int row = idx >> 3;
        int c   = idx & 7;
        uint32_t sw = SW128(row * 128 + c * 16);
        cp16(sbase + TILE_A + sw, Bt + (size_t)(bn + row) * K + k0 + c * 8);
    }
}

__global__ __launch_bounds__(256, 2)
void gemm_tc_kernel(const __half* __restrict__ A, const __half* __restrict__ Bt,
                    const float* __restrict__ bias, const float* __restrict__ mulp,
                    void* __restrict__ Cv, int M, int N, int K, int do_gelu)
{
#if TC_OK
    extern __shared__ char smem[];
    const uint32_t sb  = smem_u32(smem);
    const int tid = threadIdx.x, wid = tid >> 5, lid = tid & 31;
    const int bm = blockIdx.y * BM, bn = blockIdx.x * BN;

    if (wid == 0) { TC_ALLOC(sb + SM_TMEMPTR, 256); TC_RELINQ(); }
    if (tid == 0) { mbar_init(sb + SM_MBAR + 0, 1); mbar_init(sb + SM_MBAR + 8, 1); }
    __syncthreads();
    uint32_t tmem;
    asm volatile("ld.shared.b32 %0, [%1];" : "=r"(tmem) : "r"(sb + SM_TMEMPTR));

    const float mul = *mulp;
    const int nk = K / BK;    // 16 or 64

    uint64_t ad[NSTAGE], bd0[NSTAGE], bd1[NSTAGE];
#pragma unroll
    for (int s = 0; s < NSTAGE; s++) {
        uint32_t base = sb + s * STAGE_BYTES;
        ad[s]  = make_desc(base);
        bd0[s] = make_desc(base + TILE_A);
        bd1[s] = make_desc(base + TILE_A + 16384);
    }

    // prologue: chunks 0 and 1 into stages 0 and 1
    load_chunk(A, Bt, K, bm, bn, 0 * BK, sb + 0 * STAGE_BYTES); cp_commit();
    load_chunk(A, Bt, K, bm, bn, 1 * BK, sb + 1 * STAGE_BYTES); cp_commit();

    int wc0 = 0, wc1 = 0;
    for (int i = 0; i < nk; i++) {
        const int s = i & 1;
        if (i + 1 < nk) cp_wait<1>(); else cp_wait<0>();
        FENCE_ASYNC();
        __syncthreads();
        if (tid == 0) {
#pragma unroll
            for (int j = 0; j < 4; j++) {
                uint32_t first = (i > 0) || (j > 0);
                mma_f16_ss(tmem,       ad[s] + j * 2, bd0[s] + j * 2, MMA_IDESC, first);
                mma_f16_ss(tmem + 128, ad[s] + j * 2, bd1[s] + j * 2, MMA_IDESC, first);
            }
            tc_commit(sb + SM_MBAR + s * 8);
        }
        if (i + 2 < nk) {
            // reload stage s -> must wait for this iteration's MMAs; the stall is
            // covered by the co-resident CTA (occupancy 2).
            if (s == 0) { mbar_wait(sb + SM_MBAR + 0, wc0 & 1); wc0++; }
            else        { mbar_wait(sb + SM_MBAR + 8, wc1 & 1); wc1++; }
            load_chunk(A, Bt, K, bm, bn, (i + 2) * BK, sb + s * STAGE_BYTES);
            cp_commit();
        }
    }
    mbar_wait(sb + SM_MBAR + 0, wc0 & 1);
    mbar_wait(sb + SM_MBAR + 8, wc1 & 1);
    TC_FENCE_AFTER();

    // epilogue: 8 warps; warps 0-3 -> cols 0..127, warps 4-7 -> cols 128..255
    {
        const int nh = wid >> 2;
        const int sp = wid & 3;
        const int row = bm + sp * 32 + lid;
        const int cbase = bn + nh * 128;
        const uint32_t tb = tmem + nh * 128;
        if (do_gelu) {
            __half* crow = reinterpret_cast<__half*>(Cv) + (size_t)row * N + cbase;
#pragma unroll
            for (int c0 = 0; c0 < 128; c0 += 32) {
                uint32_t r[32];
                LDTM_X32(r, tb + c0);
                TC_WAIT_LD();
#pragma unroll
                for (int j = 0; j < 32; j += 2) {
                    float v0 = __uint_as_float(r[j + 0]) * mul + bias[cbase + c0 + j + 0];
                    float v1 = __uint_as_float(r[j + 1]) * mul + bias[cbase + c0 + j + 1];
                    v0 = 0.5f * v0 * (1.0f + erff(v0 * 0.70710678118654752f));
                    v1 = 0.5f * v1 * (1.0f + erff(v1 * 0.70710678118654752f));
                    *reinterpret_cast<__half2*>(crow + c0 + j) = __floats2half2_rn(v0, v1);
                }
            }
        } else {
            float* crow = reinterpret_cast<float*>(Cv) + (size_t)row * N + cbase;
#pragma unroll
            for (int c0 = 0; c0 < 128; c0 += 32) {
                uint32_t r[32];
                LDTM_X32(r, tb + c0);
                TC_WAIT_LD();
#pragma unroll
                for (int j = 0; j < 32; j += 4) {
                    float4 v4;
                    v4.x = __uint_as_float(r[j + 0]) * mul + bias[cbase + c0 + j + 0];
                    v4.y = __uint_as_float(r[j + 1]) * mul + bias[cbase + c0 + j + 1];
                    v4.z = __uint_as_float(r[j + 2]) * mul + bias[cbase + c0 + j + 2];
                    v4.w = __uint_as_float(r[j + 3]) * mul + bias[cbase + c0 + j + 3];
                    *reinterpret_cast<float4*>(crow + c0 + j) = v4;
                }
            }
        }
    }
    __syncthreads();
    if (wid == 0) TC_DEALLOC(tmem, 256);

#else
    // ============ SIMT fallback (correct on any arch; never used on GB300) ============
    extern __shared__ char smem[];
    float (*As)[128] = reinterpret_cast<float (*)[128]>(smem);
    float (*Bs)[128] = reinterpret_cast<float (*)[128]>(smem + 16 * 128 * 4);
    const int tid = threadIdx.x;
    const int tr = tid >> 4, tc = tid & 15;
    const float mul = *mulp;
    const int bm = blockIdx.y * BM;

    for (int hblk = 0; hblk < 2; hblk++) {
        const int bn = blockIdx.x * BN + hblk * 128;
        float acc[8][8];
#pragma unroll
        for (int i = 0; i < 8; i++)
#pragma unroll
            for (int j = 0; j < 8; j++) acc[i][j] = 0.f;
        for (int k0 = 0; k0 < K; k0 += 16) {
#pragma unroll
            for (int it = 0; it < 8; it++) {
                int idx = tid + it * 256;
                int row = idx >> 4, c = idx & 15;
                As[c][row] = __half2float(A [(size_t)(bm + row) * K + k0 + c]);
                Bs[c][row] = __half2float(Bt[(size_t)(bn + row) * K + k0 + c]);
            }
            __syncthreads();
#pragma unroll
            for (int k = 0; k < 16; k++) {
                float a[8], b[8];
#pragma unroll
                for (int i = 0; i < 4; i++) { a[i] = As[k][tr*4+i]; a[4+i] = As[k][64+tr*4+i]; }
#pragma unroll
                for (int j = 0; j < 4; j++) { b[j] = Bs[k][tc*4+j]; b[4+j] = Bs[k][64+tc*4+j]; }
#pragma unroll
                for (int i = 0; i < 8; i++)
#pragma unroll
                    for (int j = 0; j < 8; j++)
                        acc[i][j] = fmaf(a[i], b[j], acc[i][j]);
            }
            __syncthreads();
        }
#pragma unroll
        for (int i = 0; i < 8; i++) {
            int gr = bm + ((i < 4) ? (tr*4+i) : (64 + tr*4 + i - 4));
#pragma unroll
            for (int j = 0; j < 8; j++) {
                int gc = bn + ((j < 4) ? (tc*4+j) : (64 + tc*4 + j - 4));
                float v = acc[i][j] * mul + bias[gc];
                if (do_gelu) {
                    v = 0.5f * v * (1.0f + erff(v * 0.70710678118654752f));
                    reinterpret_cast<__half*>(Cv)[(size_t)gr * N + gc] = __float2half_rn(v);
                } else {
                    reinterpret_cast<float*>(Cv)[(size_t)gr * N + gc] = v;
                }
            }
        }
        __syncthreads();
    }
#endif
}

// ---------------- launcher ----------------
extern "C" void kernel_launch(void* const* d_in, const int* in_sizes, int n_in,
                              void* d_out, int out_size)
{
    const float* x    = (const float*)d_in[0];
    const float* ln1g = (const float*)d_in[1];
    const float* ln1b = (const float*)d_in[2];
    const float* w1   = (const float*)d_in[3];
    const float* b1   = (const float*)d_in[4];
    const float* ln2g = (const float*)d_in[5];
    const float* ln2b = (const float*)d_in[6];
    const float* w2   = (const float*)d_in[7];
    const float* b2   = (const float*)d_in[8];
    float* out = (float*)d_out;

    __half *xq, *h, *hq, *t1, *t2;
    float *scale, *mul;
    cudaGetSymbolAddress((void**)&xq,    g_xq);
    cudaGetSymbolAddress((void**)&h,     g_h);
    cudaGetSymbolAddress((void**)&hq,    g_hq);
    cudaGetSymbolAddress((void**)&t1,    g_t1);
    cudaGetSymbolAddress((void**)&t2,    g_t2);
    cudaGetSymbolAddress((void**)&scale, g_scale);
    cudaGetSymbolAddress((void**)&mul,   g_mul);

    static int smem_set = 0;
    if (!smem_set) {
        cudaFuncSetAttribute(gemm_tc_kernel, cudaFuncAttributeMaxDynamicSharedMemorySize,
                             SMEM_TOTAL);
        smem_set = 1;
    }

    // 1) scales
    absmean_partial_kernel<<<256, 256>>>(w1, HID * DIM, 0);
    absmean_partial_kernel<<<256, 256>>>(w2, DIM * HID, 1);
    finalize_scales_kernel<<<1, 256>>>(HID * DIM, DIM * HID);

    // 2) ternary quantization -> fp16 (exact)
    quant_kernel<<<512, 256>>>(w1, t1, scale + 0, HID * DIM);
    quant_kernel<<<512, 256>>>(w2, t2, scale + 1, DIM * HID);

    // 3) LN1 -> fp16
    ln1_kernel<<<TOK, 256>>>(x, xq, ln1g, ln1b);

    // 4) GEMM1 + bias + exact GELU -> fp16 h  (M=8192, N=4096, K=1024)
    gemm_tc_kernel<<<dim3(HID / BN, TOK / BM), 256, SMEM_TOTAL>>>(
        xq, t1, b1, mul + 0, h, TOK, HID, DIM, 1);

    // 5) LN2 (fp16 in) -> fp16
    ln2_kernel<<<TOK, 256>>>(h, hq, ln2g, ln2b);

    // 6) GEMM2 + bias -> fp32 out  (M=8192, N=1024, K=4096)
    gemm_tc_kernel<<<dim3(DIM / BN, TOK / BM), 256, SMEM_TOTAL>>>(
        hq, t2, b2, mul + 1, out, TOK, DIM, HID, 0);
}

// round 17
// speedup vs baseline: 1.3911x; 1.3911x over previous
#include <cuda_runtime.h>
#include <cuda_bf16.h>
#include <cuda_fp16.h>
#include <math.h>
#include <stdint.h>

// Problem dims (fixed): x[8,1024,1024], w1[4096,1024], w2[1024,4096]
#define DIM 1024
#define HID 4096
#define TOK 8192   // B*S

// tcgen05 is arch-SPECIFIC: only emit in sm_103a/sm_100a-family passes.
#if defined(__CUDA_ARCH_FEAT_SM103_ALL) || defined(__CUDA_ARCH_FEAT_SM100_ALL) || \
    defined(__CUDA_ARCH_FEAT_SM101_ALL) || defined(__CUDA_ARCH_FEAT_SM110_ALL)
#define TC_OK 1
#else
#define TC_OK 0
#endif

// ---------------- scratch (device globals; no allocations allowed) ----------------
__device__ __half g_xq[(size_t)TOK * DIM];   // LN1 out (fp16)      16MB
__device__ __half g_h [(size_t)TOK * HID];   // GEMM1+GELU out      64MB
__device__ __half g_hq[(size_t)TOK * HID];   // LN2 out (fp16)      64MB
__device__ __half g_t1[(size_t)HID * DIM];   // ternary w1 (fp16)    8MB
__device__ __half g_t2[(size_t)DIM * HID];   // ternary w2 (fp16)    8MB
__device__ float g_partial[2][256];
__device__ float g_scale[2];     // 1/mean|w|
__device__ float g_mul[2];       // mean|w|

// ---------------- small helpers ----------------
__device__ __forceinline__ float warp_sum(float v) {
#pragma unroll
    for (int o = 16; o > 0; o >>= 1) v += __shfl_xor_sync(0xffffffffu, v, o);
    return v;
}
__device__ __forceinline__ float block_sum_256(float v) {
    __shared__ float sh[8];
    v = warp_sum(v);
    if ((threadIdx.x & 31) == 0) sh[threadIdx.x >> 5] = v;
    __syncthreads();
    float tot = 0.f;
    if (threadIdx.x == 0) {
#pragma unroll
        for (int i = 0; i < 8; i++) tot += sh[i];
        sh[0] = tot;
    }
    __syncthreads();
    tot = sh[0];
    __syncthreads();
    return tot;
}
__device__ __forceinline__ uint32_t smem_u32(const void* p) {
    uint32_t a;
    asm("{ .reg .u64 t; cvta.to.shared.u64 t, %1; cvt.u32.u64 %0, t; }" : "=r"(a) : "l"(p));
    return a;
}
#define SW128(o) ((o) ^ (((o) >> 3) & 0x70))

static constexpr uint64_t SMEM_DESC_BASE =
    (uint64_t(2) << 61) | (uint64_t(1) << 46) | (uint64_t(64) << 32) | (uint64_t(1) << 16);
__device__ __forceinline__ uint64_t make_desc(uint32_t addr) {
    return SMEM_DESC_BASE | ((uint64_t)(addr >> 4) & 0x3FFF);
}

// ---------------- PTX wrappers ----------------
__device__ __forceinline__ void cp16(uint32_t dst, const void* src) {
    asm volatile("cp.async.cg.shared.global [%0], [%1], 16;" :: "r"(dst), "l"(src));
}
__device__ __forceinline__ void cp_commit() {
    asm volatile("cp.async.commit_group;" ::: "memory");
}
template <int N>
__device__ __forceinline__ void cp_wait() {
    asm volatile("cp.async.wait_group %0;" :: "n"(N) : "memory");
}
__device__ __forceinline__ void mbar_init(uint32_t a, uint32_t cnt) {
    asm volatile("mbarrier.init.shared.b64 [%0], %1;" :: "r"(a), "r"(cnt) : "memory");
}
__device__ __forceinline__ void mbar_wait(uint32_t a, uint32_t parity) {
    asm volatile(
        "{\n\t.reg .pred P;\n\t"
        "MW_%=:\n\t"
        "mbarrier.try_wait.parity.acquire.cta.shared::cta.b64 P, [%0], %1;\n\t"
        "@!P bra MW_%=;\n\t}"
        :: "r"(a), "r"(parity) : "memory");
}
#define FENCE_ASYNC() asm volatile("fence.proxy.async.shared::cta;" ::: "memory")

#if TC_OK
__device__ __forceinline__ void tc_commit(uint32_t mbar) {
    asm volatile(
        "tcgen05.commit.cta_group::1.mbarrier::arrive::one.shared::cluster.b64 [%0];"
        :: "r"(mbar) : "memory");
}
__device__ __forceinline__ void mma_f16_ss(uint32_t d, uint64_t a_desc, uint64_t b_desc,
                                           uint32_t idesc, uint32_t accum) {
    asm volatile(
        "{\n\t.reg .pred p;\n\t"
        "setp.ne.u32 p, %4, 0;\n\t"
        "tcgen05.mma.cta_group::1.kind::f16 [%0], %1, %2, %3, {%5, %5, %5, %5}, p;\n\t}"
        :: "r"(d), "l"(a_desc), "l"(b_desc), "r"(idesc), "r"(accum), "r"(0u)
        : "memory");
}
#define TC_ALLOC(saddr, n) \
    asm volatile("tcgen05.alloc.cta_group::1.sync.aligned.shared::cta.b32 [%0], %1;" \
                 :: "r"(saddr), "r"((uint32_t)(n)) : "memory")
#define TC_RELINQ() \
    asm volatile("tcgen05.relinquish_alloc_permit.cta_group::1.sync.aligned;")
#define TC_DEALLOC(t, n) \
    asm volatile("tcgen05.dealloc.cta_group::1.sync.aligned.b32 %0, %1;" :: "r"(t), "r"((uint32_t)(n)))
#define TC_FENCE_AFTER()  asm volatile("tcgen05.fence::after_thread_sync;" ::: "memory")
#define TC_WAIT_LD()      asm volatile("tcgen05.wait::ld.sync.aligned;" ::: "memory")

#define LDTM_X32(r, addr) \
    asm volatile( \
        "tcgen05.ld.sync.aligned.32x32b.x32.b32 " \
        "{%0, %1, %2, %3, %4, %5, %6, %7, " \
        " %8, %9, %10, %11, %12, %13, %14, %15, " \
        " %16, %17, %18, %19, %20, %21, %22, %23, " \
        " %24, %25, %26, %27, %28, %29, %30, %31}, [%32];" \
        : "=r"((r)[0]),  "=r"((r)[1]),  "=r"((r)[2]),  "=r"((r)[3]), \
          "=r"((r)[4]),  "=r"((r)[5]),  "=r"((r)[6]),  "=r"((r)[7]), \
          "=r"((r)[8]),  "=r"((r)[9]),  "=r"((r)[10]), "=r"((r)[11]), \
          "=r"((r)[12]), "=r"((r)[13]), "=r"((r)[14]), "=r"((r)[15]), \
          "=r"((r)[16]), "=r"((r)[17]), "=r"((r)[18]), "=r"((r)[19]), \
          "=r"((r)[20]), "=r"((r)[21]), "=r"((r)[22]), "=r"((r)[23]), \
          "=r"((r)[24]), "=r"((r)[25]), "=r"((r)[26]), "=r"((r)[27]), \
          "=r"((r)[28]), "=r"((r)[29]), "=r"((r)[30]), "=r"((r)[31]) \
        : "r"(addr))
#endif  // TC_OK

// ---------------- stage 0: abs-mean of weights (float4) ----------------
__global__ void absmean_partial_kernel(const float* __restrict__ w, int n, int slot) {
    float s = 0.f;
    const float4* w4 = reinterpret_cast<const float4*>(w);
    int n4 = n >> 2;
    int stride = gridDim.x * blockDim.x;
    for (int i = blockIdx.x * blockDim.x + threadIdx.x; i < n4; i += stride) {
        float4 v = w4[i];
        s += fabsf(v.x) + fabsf(v.y) + fabsf(v.z) + fabsf(v.w);
    }
    s = block_sum_256(s);
    if (threadIdx.x == 0) g_partial[slot][blockIdx.x] = s;
}
__global__ void finalize_scales_kernel(int n1, int n2) {
    for (int slot = 0; slot < 2; slot++) {
        float v = g_partial[slot][threadIdx.x];
        float tot = block_sum_256(v);
        if (threadIdx.x == 0) {
            float mean = tot / (float)(slot == 0 ? n1 : n2);
            mean = fmaxf(mean, 1e-5f);
            g_mul[slot]   = mean;
            g_scale[slot] = 1.0f / mean;
        }
        __syncthreads();
    }
}

// ---------------- stage 1: ternary quantization -> fp16 (exact for {-1,0,1}) ------
__global__ void quant_kernel(const float* __restrict__ w, __half* __restrict__ t,
                             const float* __restrict__ scalep, int n) {
    float s = *scalep;
    const float4* w4 = reinterpret_cast<const float4*>(w);
    __half2* t2 = reinterpret_cast<__half2*>(t);
    int n4 = n >> 2;
    int stride = gridDim.x * blockDim.x;
    for (int i = blockIdx.x * blockDim.x + threadIdx.x; i < n4; i += stride) {
        float4 v = w4[i];
        float q0 = fmaxf(-1.f, fminf(1.f, rintf(v.x * s)));
        float q1 = fmaxf(-1.f, fminf(1.f, rintf(v.y * s)));
        float q2 = fmaxf(-1.f, fminf(1.f, rintf(v.z * s)));
        float q3 = fmaxf(-1.f, fminf(1.f, rintf(v.w * s)));
        t2[i * 2 + 0] = __floats2half2_rn(q0, q1);
        t2[i * 2 + 1] = __floats2half2_rn(q2, q3);
    }
}

// ---------------- LN1 (fp32 in, D=1024) -> fp16 ----------------
__global__ __launch_bounds__(256) void ln1_kernel(
    const float* __restrict__ x, __half* __restrict__ o,
    const float* __restrict__ gamma, const float* __restrict__ beta)
{
    constexpr int D = DIM;
    const int row = blockIdx.x;
    const float4* xr = reinterpret_cast<const float4*>(x + (size_t)row * D);
    float4 v = xr[threadIdx.x];
    float s = v.x + v.y + v.z + v.w;
    float sq = v.x * v.x + v.y * v.y + v.z * v.z + v.w * v.w;
    __shared__ float sh[16];
    float ws = warp_sum(s), wq = warp_sum(sq);
    if ((threadIdx.x & 31) == 0) { sh[threadIdx.x >> 5] = ws; sh[8 + (threadIdx.x >> 5)] = wq; }
    __syncthreads();
    __shared__ float s_mu, s_rstd;
    if (threadIdx.x == 0) {
        float ts = 0.f, tq = 0.f;
#pragma unroll
        for (int i = 0; i < 8; i++) { ts += sh[i]; tq += sh[8 + i]; }
        float mu = ts / (float)D;
        float var = tq / (float)D - mu * mu;
        s_mu = mu;
        s_rstd = rsqrtf(var + 1e-5f);
    }
    __syncthreads();
    const float mu = s_mu, rstd = s_rstd;
    const float4 g = reinterpret_cast<const float4*>(gamma)[threadIdx.x];
    const float4 b = reinterpret_cast<const float4*>(beta)[threadIdx.x];
    __half2* o2 = reinterpret_cast<__half2*>(o + (size_t)row * D);
    float o0 = (v.x - mu) * rstd * g.x + b.x;
    float o1 = (v.y - mu) * rstd * g.y + b.y;
    float o2v = (v.z - mu) * rstd * g.z + b.z;
    float o3 = (v.w - mu) * rstd * g.w + b.w;
    o2[threadIdx.x * 2 + 0] = __floats2half2_rn(o0, o1);
    o2[threadIdx.x * 2 + 1] = __floats2half2_rn(o2v, o3);
}

// ---------------- LN2 (fp16 in, D=4096) -> fp16 ----------------
__global__ __launch_bounds__(256) void ln2_kernel(
    const __half* __restrict__ x, __half* __restrict__ o,
    const float* __restrict__ gamma, const float* __restrict__ beta)
{
    constexpr int D = HID;
    const int row = blockIdx.x;
    const __half2* xr = reinterpret_cast<const __half2*>(x + (size_t)row * D);
    float2 f[8];
    float s = 0.f, sq = 0.f;
#pragma unroll
    for (int i = 0; i < 8; i++) {
        __half2 v = xr[threadIdx.x + i * 256];
        f[i] = __half22float2(v);
        s  += f[i].x + f[i].y;
        sq += f[i].x * f[i].x + f[i].y * f[i].y;
    }
    __shared__ float sh[16];
    float ws = warp_sum(s), wq = warp_sum(sq);
    if ((threadIdx.x & 31) == 0) { sh[threadIdx.x >> 5] = ws; sh[8 + (threadIdx.x >> 5)] = wq; }
    __syncthreads();
    __shared__ float s_mu, s_rstd;
    if (threadIdx.x == 0) {
        float ts = 0.f, tq = 0.f;
#pragma unroll
        for (int i = 0; i < 8; i++) { ts += sh[i]; tq += sh[8 + i]; }
        float mu = ts / (float)D;
        float var = tq / (float)D - mu * mu;
        s_mu = mu;
        s_rstd = rsqrtf(var + 1e-5f);
    }
    __syncthreads();
    const float mu = s_mu, rstd = s_rstd;
    const float2* g2p = reinterpret_cast<const float2*>(gamma);
    const float2* b2p = reinterpret_cast<const float2*>(beta);
    __half2* o2 = reinterpret_cast<__half2*>(o + (size_t)row * D);
#pragma unroll
    for (int i = 0; i < 8; i++) {
        int idx = threadIdx.x + i * 256;
        float2 g = g2p[idx], b = b2p[idx];
        float v0 = (f[i].x - mu) * rstd * g.x + b.x;
        float v1 = (f[i].y - mu) * rstd * g.y + b.y;
        o2[idx] = __floats2half2_rn(v0, v1);
    }
}

// ---------------- tcgen05 GEMM: 256x256 tiles, fp16, 3-stage lag-2, occ=1 --------
// C[M,N] = (A[M,K] . B[N,K]^T)*mul + bias; do_gelu -> exact GELU + fp16 out, else fp32 out
// 4 quadrants of 128x128 MMAs; 64KB chunks (A 32K + B 32K); lag-2 reload keeps the
// MMA-done wait off the load path (proven R13); B rows shared by 256 A rows (-33% traffic).
#define BM 256
#define BN 256
#define BK 64
#define TILE_A       32768                   // 256 rows x 128B (fp16)
#define TILE_B       32768                   // 256 rows x 128B
#define STAGE_BYTES  (TILE_A + TILE_B)       // 64KB
#define NSTAGE 3
#define SM_TMEMPTR   (NSTAGE * STAGE_BYTES)  // 196608
#define SM_MBAR      (SM_TMEMPTR + 8)        // 3 mbars
#define SMEM_TOTAL   (SM_TMEMPTR + 64)
// idesc: f32 accum (dtype=1), fp16 A/B (atype=btype=0), N=128, M=128
#define MMA_IDESC 0x8200010u

__device__ __forceinline__ void load_chunk(
    const __half* __restrict__ A, const __half* __restrict__ Bt,
    int K, int bm, int bn, int k0, uint32_t sbase)
{
    const int t = threadIdx.x;
#pragma unroll
    for (int i = 0; i < 8; i++) {
        int idx = t + (i << 8);   // A rows 0..255, 8x16B chunks each
        int row = idx >> 3;
        int c   = idx & 7;
        uint32_t sw = SW128(row * 128 + c * 16);
        cp16(sbase + sw, A + (size_t)(bm + row) * K + k0 + c * 8);
    }
#pragma unroll
    for (int i = 0; i < 8; i++) {
        int idx = t + (i << 8);   // B rows 0..255
        int row = idx >> 3;
        int c   = idx & 7;
        uint32_t sw = SW128(row * 128 + c * 16);
        cp16(sbase + TILE_A + sw, Bt + (size_t)(bn + row) * K + k0 + c * 8);
    }
}

__global__ __launch_bounds__(256)
void gemm_tc_kernel(const __half* __restrict__ A, const __half* __restrict__ Bt,
                    const float* __restrict__ bias, const float* __restrict__ mulp,
                    void* __restrict__ Cv, int M, int N, int K, int do_gelu)
{
#if TC_OK
    extern __shared__ char smem[];
    const uint32_t sb  = smem_u32(smem);
    const int tid = threadIdx.x, wid = tid >> 5, lid = tid & 31;
    const int bm = blockIdx.y * BM, bn = blockIdx.x * BN;

    if (wid == 0) { TC_ALLOC(sb + SM_TMEMPTR, 512); TC_RELINQ(); }
    if (tid == 0) {
        mbar_init(sb + SM_MBAR + 0, 1);
        mbar_init(sb + SM_MBAR + 8, 1);
        mbar_init(sb + SM_MBAR + 16, 1);
    }
    __syncthreads();
    uint32_t tmem;
    asm volatile("ld.shared.b32 %0, [%1];" : "=r"(tmem) : "r"(sb + SM_TMEMPTR));

    const float mul = *mulp;
    const int nk = K / BK;    // 16 or 64

    uint64_t ad[NSTAGE][2], bd[NSTAGE][2];
#pragma unroll
    for (int s = 0; s < NSTAGE; s++) {
        uint32_t base = sb + s * STAGE_BYTES;
#pragma unroll
        for (int hh = 0; hh < 2; hh++) {
            ad[s][hh] = make_desc(base + hh * 16384);
            bd[s][hh] = make_desc(base + TILE_A + hh * 16384);
        }
    }

    // prologue: chunks 0 and 1 into stages 0 and 1
    load_chunk(A, Bt, K, bm, bn, 0 * BK, sb + 0 * STAGE_BYTES); cp_commit();
    load_chunk(A, Bt, K, bm, bn, 1 * BK, sb + 1 * STAGE_BYTES); cp_commit();

    int wcs0 = 0, wcs1 = 0, wcs2 = 0;
    for (int i = 0; i < nk; i++) {
        const int s = i % NSTAGE;
        if (i + 1 < nk) cp_wait<1>(); else cp_wait<0>();
        FENCE_ASYNC();
        __syncthreads();
        if (tid == 0) {
#pragma unroll
            for (int j = 0; j < 4; j++) {
                uint32_t first = (i > 0) || (j > 0);
#pragma unroll
                for (int mh = 0; mh < 2; mh++) {
#pragma unroll
                    for (int nh = 0; nh < 2; nh++) {
                        uint32_t d = tmem + (uint32_t)(mh * 256 + nh * 128);
                        mma_f16_ss(d, ad[s][mh] + j * 2, bd[s][nh] + j * 2, MMA_IDESC, first);
                    }
                }
            }
            tc_commit(sb + SM_MBAR + s * 8);
        }
        // Lag-2 reload: chunk i+2 -> stage (i-1)%3, hazard is MMA_{i-1} (a full
        // period old) -> the mbar wait is ~free.
        if (i + 2 < nk) {
            const int st = (i + 2) % NSTAGE;
            if (i >= 1) {
                if (st == 0)      { mbar_wait(sb + SM_MBAR + 0,  wcs0 & 1); wcs0++; }
                else if (st == 1) { mbar_wait(sb + SM_MBAR + 8,  wcs1 & 1); wcs1++; }
                else              { mbar_wait(sb + SM_MBAR + 16, wcs2 & 1); wcs2++; }
            }
            load_chunk(A, Bt, K, bm, bn, (i + 2) * BK, sb + st * STAGE_BYTES);
            cp_commit();
        }
    }
    mbar_wait(sb + SM_MBAR + 0,  wcs0 & 1);
    mbar_wait(sb + SM_MBAR + 8,  wcs1 & 1);
    mbar_wait(sb + SM_MBAR + 16, wcs2 & 1);
    TC_FENCE_AFTER();

    // epilogue: 8 warps. warps 0-3 -> m-half 0, warps 4-7 -> m-half 1;
    // each warp covers its 32-row subpartition across all 256 columns.
    {
        const int mh = wid >> 2;
        const int sp = wid & 3;
        const int row = bm + mh * 128 + sp * 32 + lid;
        const uint32_t tb = tmem + (uint32_t)(mh * 256);
        if (do_gelu) {
            __half* crow = reinterpret_cast<__half*>(Cv) + (size_t)row * N + bn;
#pragma unroll
            for (int c0 = 0; c0 < 256; c0 += 32) {
                uint32_t r[32];
                LDTM_X32(r, tb + c0);
                TC_WAIT_LD();
#pragma unroll
                for (int j = 0; j < 32; j += 2) {
                    float v0 = __uint_as_float(r[j + 0]) * mul + bias[bn + c0 + j + 0];
                    float v1 = __uint_as_float(r[j + 1]) * mul + bias[bn + c0 + j + 1];
                    v0 = 0.5f * v0 * (1.0f + erff(v0 * 0.70710678118654752f));
                    v1 = 0.5f * v1 * (1.0f + erff(v1 * 0.70710678118654752f));
                    *reinterpret_cast<__half2*>(crow + c0 + j) = __floats2half2_rn(v0, v1);
                }
            }
        } else {
            float* crow = reinterpret_cast<float*>(Cv) + (size_t)row * N + bn;
#pragma unroll
            for (int c0 = 0; c0 < 256; c0 += 32) {
                uint32_t r[32];
                LDTM_X32(r, tb + c0);
                TC_WAIT_LD();
#pragma unroll
                for (int j = 0; j < 32; j += 4) {
                    float4 v4;
                    v4.x = __uint_as_float(r[j + 0]) * mul + bias[bn + c0 + j + 0];
                    v4.y = __uint_as_float(r[j + 1]) * mul + bias[bn + c0 + j + 1];
                    v4.z = __uint_as_float(r[j + 2]) * mul + bias[bn + c0 + j + 2];
                    v4.w = __uint_as_float(r[j + 3]) * mul + bias[bn + c0 + j + 3];
                    *reinterpret_cast<float4*>(crow + c0 + j) = v4;
                }
            }
        }
    }
    __syncthreads();
    if (wid == 0) TC_DEALLOC(tmem, 512);

#else
    // ============ SIMT fallback (correct on any arch; never used on GB300) ============
    extern __shared__ char smem[];
    float (*As)[128] = reinterpret_cast<float (*)[128]>(smem);
    float (*Bs)[128] = reinterpret_cast<float (*)[128]>(smem + 16 * 128 * 4);
    const int tid = threadIdx.x;
    const int tr = tid >> 4, tc = tid & 15;
    const float mul = *mulp;

    for (int mblk = 0; mblk < 2; mblk++) {
        const int bm = blockIdx.y * BM + mblk * 128;
        for (int nblk = 0; nblk < 2; nblk++) {
            const int bn = blockIdx.x * BN + nblk * 128;
            float acc[8][8];
#pragma unroll
            for (int i = 0; i < 8; i++)
#pragma unroll
                for (int j = 0; j < 8; j++) acc[i][j] = 0.f;
            for (int k0 = 0; k0 < K; k0 += 16) {
#pragma unroll
                for (int it = 0; it < 8; it++) {
                    int idx = tid + it * 256;
                    int row = idx >> 4, c = idx & 15;
                    As[c][row] = __half2float(A [(size_t)(bm + row) * K + k0 + c]);
                    Bs[c][row] = __half2float(Bt[(size_t)(bn + row) * K + k0 + c]);
                }
                __syncthreads();
#pragma unroll
                for (int k = 0; k < 16; k++) {
                    float a[8], b[8];
#pragma unroll
                    for (int i = 0; i < 4; i++) { a[i] = As[k][tr*4+i]; a[4+i] = As[k][64+tr*4+i]; }
#pragma unroll
                    for (int j = 0; j < 4; j++) { b[j] = Bs[k][tc*4+j]; b[4+j] = Bs[k][64+tc*4+j]; }
#pragma unroll
                    for (int i = 0; i < 8; i++)
#pragma unroll
                        for (int j = 0; j < 8; j++)
                            acc[i][j] = fmaf(a[i], b[j], acc[i][j]);
                }
                __syncthreads();
            }
#pragma unroll
            for (int i = 0; i < 8; i++) {
                int gr = bm + ((i < 4) ? (tr*4+i) : (64 + tr*4 + i - 4));
#pragma unroll
                for (int j = 0; j < 8; j++) {
                    int gc = bn + ((j < 4) ? (tc*4+j) : (64 + tc*4 + j - 4));
                    float v = acc[i][j] * mul + bias[gc];
                    if (do_gelu) {
                        v = 0.5f * v * (1.0f + erff(v * 0.70710678118654752f));
                        reinterpret_cast<__half*>(Cv)[(size_t)gr * N + gc] = __float2half_rn(v);
                    } else {
                        reinterpret_cast<float*>(Cv)[(size_t)gr * N + gc] = v;
                    }
                }
            }
            __syncthreads();
        }
    }
#endif
}

// ---------------- launcher ----------------
extern "C" void kernel_launch(void* const* d_in, const int* in_sizes, int n_in,
                              void* d_out, int out_size)
{
    const float* x    = (const float*)d_in[0];
    const float* ln1g = (const float*)d_in[1];
    const float* ln1b = (const float*)d_in[2];
    const float* w1   = (const float*)d_in[3];
    const float* b1   = (const float*)d_in[4];
    const float* ln2g = (const float*)d_in[5];
    const float* ln2b = (const float*)d_in[6];
    const float* w2   = (const float*)d_in[7];
    const float* b2   = (const float*)d_in[8];
    float* out = (float*)d_out;

    __half *xq, *h, *hq, *t1, *t2;
    float *scale, *mul;
    cudaGetSymbolAddress((void**)&xq,    g_xq);
    cudaGetSymbolAddress((void**)&h,     g_h);
    cudaGetSymbolAddress((void**)&hq,    g_hq);
    cudaGetSymbolAddress((void**)&t1,    g_t1);
    cudaGetSymbolAddress((void**)&t2,    g_t2);
    cudaGetSymbolAddress((void**)&scale, g_scale);
    cudaGetSymbolAddress((void**)&mul,   g_mul);

    static int smem_set = 0;
    if (!smem_set) {
        cudaFuncSetAttribute(gemm_tc_kernel, cudaFuncAttributeMaxDynamicSharedMemorySize,
                             SMEM_TOTAL);
        smem_set = 1;
    }

    // 1) scales
    absmean_partial_kernel<<<256, 256>>>(w1, HID * DIM, 0);
    absmean_partial_kernel<<<256, 256>>>(w2, DIM * HID, 1);
    finalize_scales_kernel<<<1, 256>>>(HID * DIM, DIM * HID);

    // 2) ternary quantization -> fp16 (exact)
    quant_kernel<<<512, 256>>>(w1, t1, scale + 0, HID * DIM);
    quant_kernel<<<512, 256>>>(w2, t2, scale + 1, DIM * HID);

    // 3) LN1 -> fp16
    ln1_kernel<<<TOK, 256>>>(x, xq, ln1g, ln1b);

    // 4) GEMM1 + bias + exact GELU -> fp16 h  (M=8192, N=4096, K=1024) — 512 tiles
    gemm_tc_kernel<<<dim3(HID / BN, TOK / BM), 256, SMEM_TOTAL>>>(
        xq, t1, b1, mul + 0, h, TOK, HID, DIM, 1);

    // 5) LN2 (fp16 in) -> fp16
    ln2_kernel<<<TOK, 256>>>(h, hq, ln2g, ln2b);

    // 6) GEMM2 + bias -> fp32 out  (M=8192, N=1024, K=4096) — 128 tiles (single wave)
    gemm_tc_kernel<<<dim3(DIM / BN, TOK / BM), 256, SMEM_TOTAL>>>(
        hq, t2, b2, mul + 1, out, TOK, DIM, HID, 0);
}